// round 9
// baseline (speedup 1.0000x reference)
#include <cuda_runtime.h>
#include <math.h>
#include <stdint.h>

// ---------------- problem dims ----------------
#define MB   8
#define SS   1024
#define HH   1536
#define NHh  8
#define HD   96
#define AHd  768
#define KK   7
#define IM   3072
#define MROWS (MB*SS)          // 8192

// ---------------- scratch ----------------
__device__ float g_q   [MROWS*AHd];
__device__ float g_k   [MROWS*AHd];
__device__ float g_v   [MROWS*AHd];
__device__ float g_co  [MROWS*AHd];
__device__ float g_dconv[MROWS*HH];
__device__ float g_sep [MROWS*AHd];
__device__ float g_ck  [MROWS*56];
__device__ float g_ctx [MROWS*HH];
__device__ float g_tmp [MROWS*HH];
__device__ float g_inter[MROWS*IM];
__device__ float g_attn[MROWS*HH];
__device__ float g_layer[MROWS*HH];
__device__ float g_poolp[MB*8*HH];

// ---------------- streams/events (created at load time) ----------------
struct StreamInit {
    cudaStream_t s2;
    cudaEvent_t evF, evA, evB;
    StreamInit() {
        cudaStreamCreateWithFlags(&s2, cudaStreamNonBlocking);
        cudaEventCreateWithFlags(&evF, cudaEventDisableTiming);
        cudaEventCreateWithFlags(&evA, cudaEventDisableTiming);
        cudaEventCreateWithFlags(&evB, cudaEventDisableTiming);
    }
};
static StreamInit g_si;

// ---------------- PTX helpers ----------------
__device__ __forceinline__ uint32_t sptr(const void* p) {
    return (uint32_t)__cvta_generic_to_shared(p);
}
#define CP16(dst, src) \
    asm volatile("cp.async.cg.shared.global [%0], [%1], 16;" :: "r"(dst), "l"(src))
#define CP_COMMIT() asm volatile("cp.async.commit_group;" ::: "memory")
#define CP_WAIT(n)  asm volatile("cp.async.wait_group %0;" :: "n"(n) : "memory")

__device__ __forceinline__ void mma_tf32(float* d, const uint32_t* a, const uint32_t* b) {
    asm volatile(
        "mma.sync.aligned.m16n8k8.row.col.f32.tf32.tf32.f32 "
        "{%0,%1,%2,%3}, {%4,%5,%6,%7}, {%8,%9}, {%0,%1,%2,%3};"
        : "+f"(d[0]), "+f"(d[1]), "+f"(d[2]), "+f"(d[3])
        : "r"(a[0]), "r"(a[1]), "r"(a[2]), "r"(a[3]), "r"(b[0]), "r"(b[1]));
}

// ============================================================================
// tf32 mma GEMM, 3-buffer ring, single barrier per iteration.
// op: 0 = bias, 1 = bias+gelu, 2 = (x+bias)*aux
// ============================================================================
#define PA   36
#define PB   136
#define ASZ  (128*PA)
#define BSZ  (32*PB)
#define NSTG 3
#define GEMM_SMEM (NSTG*(ASZ+BSZ)*4)

struct GemmSet { const float* W; const float* bias; float* C; };

__device__ __forceinline__ void gemm_body(
    const float* __restrict__ A, const float* __restrict__ W,
    const float* __restrict__ bias, float* __restrict__ C,
    const float* __restrict__ aux,
    int N, int Kd, int op, int m0, int n0, float* sm)
{
    float* Abase = sm;
    float* Bbase = sm + NSTG * ASZ;

    const int tid = threadIdx.x;
    const int wid = tid >> 5, lane = tid & 31;
    const int wr = wid >> 2, wc = wid & 3;
    const int g = lane >> 2, tg = lane & 3;
    const int nkb = Kd >> 5;

    float acc[4][4][4];
#pragma unroll
    for (int i = 0; i < 4; i++)
#pragma unroll
        for (int j = 0; j < 4; j++)
#pragma unroll
            for (int c = 0; c < 4; c++) acc[i][j][c] = 0.f;

    auto issue = [&](int kb) {
        int s = kb % NSTG;
        float* As = Abase + s * ASZ;
        float* Bs = Bbase + s * BSZ;
        const float* ag = A + (size_t)m0 * Kd + kb * 32;
        const float* bg = W + (size_t)(kb * 32) * N + n0;
#pragma unroll
        for (int t = 0; t < 4; t++) {
            int sA = tid + t * 256;
            int r  = sA >> 3,  c  = (sA & 7) << 2;
            CP16(sptr(As + r * PA + c), ag + (size_t)r * Kd + c);
            int rb = sA >> 5,  cb = (sA & 31) << 2;
            CP16(sptr(Bs + rb * PB + cb), bg + (size_t)rb * N + cb);
        }
    };

    issue(0); CP_COMMIT();
    issue(1); CP_COMMIT();

    for (int kb = 0; kb < nkb; kb++) {
        CP_WAIT(1);          // tile kb resident (kb+1 may still be in flight)
        __syncthreads();     // all warps finished computing kb-1; kb visible
        if (kb + 2 < nkb) {  // prefetch into the buffer freed by compute(kb-1)
            issue(kb + 2);
            CP_COMMIT();
        }
        int s = kb % NSTG;
        const uint32_t* As = (const uint32_t*)(Abase + s * ASZ);
        const uint32_t* Bs = (const uint32_t*)(Bbase + s * BSZ);
#pragma unroll
        for (int kk = 0; kk < 32; kk += 8) {
            uint32_t af[4][4], bf[4][2];
#pragma unroll
            for (int mt = 0; mt < 4; mt++) {
                int mb = wr * 64 + mt * 16 + g;
                af[mt][0] = As[mb * PA + kk + tg];
                af[mt][1] = As[(mb + 8) * PA + kk + tg];
                af[mt][2] = As[mb * PA + kk + tg + 4];
                af[mt][3] = As[(mb + 8) * PA + kk + tg + 4];
            }
#pragma unroll
            for (int nt = 0; nt < 4; nt++) {
                int nb = wc * 32 + nt * 8 + g;
                bf[nt][0] = Bs[(kk + tg) * PB + nb];
                bf[nt][1] = Bs[(kk + tg + 4) * PB + nb];
            }
#pragma unroll
            for (int mt = 0; mt < 4; mt++)
#pragma unroll
                for (int nt = 0; nt < 4; nt++)
                    mma_tf32(acc[mt][nt], af[mt], bf[nt]);
        }
    }

    float bb[4][2];
#pragma unroll
    for (int nt = 0; nt < 4; nt++) {
        int col = n0 + wc * 32 + nt * 8 + 2 * tg;
        bb[nt][0] = bias[col];
        bb[nt][1] = bias[col + 1];
    }
#pragma unroll
    for (int mt = 0; mt < 4; mt++) {
#pragma unroll
        for (int nt = 0; nt < 4; nt++) {
            int row = m0 + wr * 64 + mt * 16 + g;
            int col = n0 + wc * 32 + nt * 8 + 2 * tg;
            float v0 = acc[mt][nt][0] + bb[nt][0];
            float v1 = acc[mt][nt][1] + bb[nt][1];
            float v2 = acc[mt][nt][2] + bb[nt][0];
            float v3 = acc[mt][nt][3] + bb[nt][1];
            if (op == 1) {
                v0 = 0.5f * v0 * (1.f + erff(v0 * 0.70710678118654752f));
                v1 = 0.5f * v1 * (1.f + erff(v1 * 0.70710678118654752f));
                v2 = 0.5f * v2 * (1.f + erff(v2 * 0.70710678118654752f));
                v3 = 0.5f * v3 * (1.f + erff(v3 * 0.70710678118654752f));
            } else if (op == 2) {
                const float* a0 = aux + (size_t)row * N + col;
                const float* a1 = aux + (size_t)(row + 8) * N + col;
                v0 *= a0[0]; v1 *= a0[1]; v2 *= a1[0]; v3 *= a1[1];
            }
            *(float2*)(C + (size_t)row * N + col)       = make_float2(v0, v1);
            *(float2*)(C + (size_t)(row + 8) * N + col) = make_float2(v2, v3);
        }
    }
}

__global__ void __launch_bounds__(256, 2) mma_gemm(
    const float* __restrict__ A, const float* __restrict__ W,
    const float* __restrict__ bias, float* __restrict__ C,
    const float* __restrict__ aux, int N, int Kd, int op)
{
    extern __shared__ float sm[];
    gemm_body(A, W, bias, C, aux, N, Kd, op, blockIdx.y * 128, blockIdx.x * 128, sm);
}

__global__ void __launch_bounds__(256, 2) mma_gemm_multi(
    const float* __restrict__ A, GemmSet s0, GemmSet s1, GemmSet s2, GemmSet s3,
    int N, int Kd)
{
    extern __shared__ float sm[];
    GemmSet s = (blockIdx.z == 0) ? s0 : (blockIdx.z == 1) ? s1 : (blockIdx.z == 2) ? s2 : s3;
    gemm_body(A, s.W, s.bias, s.C, nullptr, N, Kd, 0, blockIdx.y * 128, blockIdx.x * 128, sm);
}

// ============================================================================
// Fused flash attention (unchanged)
// ============================================================================
#define FQP 100
#define FKP 132
#define FVP 104
#define FL_SMEM ((128*FQP + 128*FKP + 128*FVP + 2*128*4)*4)

__global__ void __launch_bounds__(256) flash_attn(
    const float* __restrict__ Q, const float* __restrict__ K,
    const float* __restrict__ V, float* __restrict__ C)
{
    extern __shared__ float sm[];
    float* Qs   = sm;
    float* Ks   = Qs + 128 * FQP;
    float* Vs   = Ks + 128 * FKP;
    float* redm = Vs + 128 * FVP;
    float* reds = redm + 128 * 4;

    const int tid = threadIdx.x;
    const int wid = tid >> 5, lane = tid & 31;
    const int wr = wid >> 2, wc = wid & 3;
    const int g = lane >> 2, tg = lane & 3;
    const int bz = blockIdx.y, b = bz >> 3, h = bz & 7;
    const int m0 = blockIdx.x * 128;

    const float* qg = Q + (size_t)b * SS * AHd + h * HD;
    const float* kg = K + (size_t)b * SS * AHd + h * HD;
    const float* vg = V + (size_t)b * SS * AHd + h * HD;

#pragma unroll
    for (int t = 0; t < 12; t++) {
        int s = tid + t * 256;
        int r = s / 24, cc = (s % 24) * 4;
        CP16(sptr(Qs + r * FQP + cc), qg + (size_t)(m0 + r) * AHd + cc);
    }
    CP_COMMIT();

    float m_i[4][2], l_i[4][2];
    float acc_o[4][3][4];
#pragma unroll
    for (int i = 0; i < 4; i++) {
        m_i[i][0] = m_i[i][1] = -1e30f;
        l_i[i][0] = l_i[i][1] = 0.f;
#pragma unroll
        for (int j = 0; j < 3; j++)
#pragma unroll
            for (int c = 0; c < 4; c++) acc_o[i][j][c] = 0.f;
    }

    for (int kt = 0; kt < 8; kt++) {
#pragma unroll
        for (int t = 0; t < 12; t++) {
            int s = tid + t * 256;
            int r = s / 24, cc = (s % 24) * 4;
            CP16(sptr(Ks + r * FKP + cc), kg + (size_t)(kt * 128 + r) * AHd + cc);
        }
        CP_COMMIT();
#pragma unroll
        for (int t = 0; t < 12; t++) {
            int s = tid + t * 256;
            int r = s / 24, cc = (s % 24) * 4;
            CP16(sptr(Vs + r * FVP + cc), vg + (size_t)(kt * 128 + r) * AHd + cc);
        }
        CP_COMMIT();
        CP_WAIT(1);
        __syncthreads();

        float sa[4][4][4];
#pragma unroll
        for (int i = 0; i < 4; i++)
#pragma unroll
            for (int j = 0; j < 4; j++)
#pragma unroll
                for (int c = 0; c < 4; c++) sa[i][j][c] = 0.f;

        const uint32_t* Qu = (const uint32_t*)Qs;
        const uint32_t* Ku = (const uint32_t*)Ks;
#pragma unroll
        for (int kk = 0; kk < 96; kk += 8) {
            uint32_t af[4][4], bf[4][2];
#pragma unroll
            for (int mt = 0; mt < 4; mt++) {
                int mb = wr * 64 + mt * 16 + g;
                af[mt][0] = Qu[mb * FQP + kk + tg];
                af[mt][1] = Qu[(mb + 8) * FQP + kk + tg];
                af[mt][2] = Qu[mb * FQP + kk + tg + 4];
                af[mt][3] = Qu[(mb + 8) * FQP + kk + tg + 4];
            }
#pragma unroll
            for (int nt = 0; nt < 4; nt++) {
                int nb = wc * 32 + nt * 8 + g;
                bf[nt][0] = Ku[nb * FKP + kk + tg];
                bf[nt][1] = Ku[nb * FKP + kk + tg + 4];
            }
#pragma unroll
            for (int mt = 0; mt < 4; mt++)
#pragma unroll
                for (int nt = 0; nt < 4; nt++)
                    mma_tf32(sa[mt][nt], af[mt], bf[nt]);
        }
        const float scale = 0.10206207261596576f;
#pragma unroll
        for (int mt = 0; mt < 4; mt++)
#pragma unroll
            for (int nt = 0; nt < 4; nt++)
#pragma unroll
                for (int c = 0; c < 4; c++) sa[mt][nt][c] *= scale;

        float rmax[4][2];
#pragma unroll
        for (int mt = 0; mt < 4; mt++) {
            float m0v = fmaxf(sa[mt][0][0], sa[mt][0][1]);
            float m1v = fmaxf(sa[mt][0][2], sa[mt][0][3]);
#pragma unroll
            for (int nt = 1; nt < 4; nt++) {
                m0v = fmaxf(m0v, fmaxf(sa[mt][nt][0], sa[mt][nt][1]));
                m1v = fmaxf(m1v, fmaxf(sa[mt][nt][2], sa[mt][nt][3]));
            }
            m0v = fmaxf(m0v, __shfl_xor_sync(0xffffffffu, m0v, 1));
            m0v = fmaxf(m0v, __shfl_xor_sync(0xffffffffu, m0v, 2));
            m1v = fmaxf(m1v, __shfl_xor_sync(0xffffffffu, m1v, 1));
            m1v = fmaxf(m1v, __shfl_xor_sync(0xffffffffu, m1v, 2));
            rmax[mt][0] = m0v; rmax[mt][1] = m1v;
        }
        if (tg == 0) {
#pragma unroll
            for (int mt = 0; mt < 4; mt++) {
                int r0 = wr * 64 + mt * 16 + g;
                redm[r0 * 4 + wc] = rmax[mt][0];
                redm[(r0 + 8) * 4 + wc] = rmax[mt][1];
            }
        }
        __syncthreads();

        float alpha[4][2], mnew[4][2];
#pragma unroll
        for (int mt = 0; mt < 4; mt++) {
#pragma unroll
            for (int hf = 0; hf < 2; hf++) {
                int row = wr * 64 + mt * 16 + g + hf * 8;
                float4 r4 = *(float4*)&redm[row * 4];
                float gm = fmaxf(fmaxf(r4.x, r4.y), fmaxf(r4.z, r4.w));
                float mn = fmaxf(m_i[mt][hf], gm);
                alpha[mt][hf] = __expf(m_i[mt][hf] - mn);
                mnew[mt][hf] = mn;
                m_i[mt][hf] = mn;
            }
        }

        float rsum[4][2];
#pragma unroll
        for (int mt = 0; mt < 4; mt++) { rsum[mt][0] = 0.f; rsum[mt][1] = 0.f; }
#pragma unroll
        for (int mt = 0; mt < 4; mt++)
#pragma unroll
            for (int nt = 0; nt < 4; nt++) {
                sa[mt][nt][0] = __expf(sa[mt][nt][0] - mnew[mt][0]);
                sa[mt][nt][1] = __expf(sa[mt][nt][1] - mnew[mt][0]);
                sa[mt][nt][2] = __expf(sa[mt][nt][2] - mnew[mt][1]);
                sa[mt][nt][3] = __expf(sa[mt][nt][3] - mnew[mt][1]);
                rsum[mt][0] += sa[mt][nt][0] + sa[mt][nt][1];
                rsum[mt][1] += sa[mt][nt][2] + sa[mt][nt][3];
            }
#pragma unroll
        for (int mt = 0; mt < 4; mt++) {
            rsum[mt][0] += __shfl_xor_sync(0xffffffffu, rsum[mt][0], 1);
            rsum[mt][0] += __shfl_xor_sync(0xffffffffu, rsum[mt][0], 2);
            rsum[mt][1] += __shfl_xor_sync(0xffffffffu, rsum[mt][1], 1);
            rsum[mt][1] += __shfl_xor_sync(0xffffffffu, rsum[mt][1], 2);
        }
        if (tg == 0) {
#pragma unroll
            for (int mt = 0; mt < 4; mt++) {
                int r0 = wr * 64 + mt * 16 + g;
                reds[r0 * 4 + wc] = rsum[mt][0];
                reds[(r0 + 8) * 4 + wc] = rsum[mt][1];
            }
        }
        __syncthreads();
#pragma unroll
        for (int mt = 0; mt < 4; mt++) {
#pragma unroll
            for (int hf = 0; hf < 2; hf++) {
                int row = wr * 64 + mt * 16 + g + hf * 8;
                float4 r4 = *(float4*)&reds[row * 4];
                float rs = r4.x + r4.y + r4.z + r4.w;
                l_i[mt][hf] = l_i[mt][hf] * alpha[mt][hf] + rs;
            }
#pragma unroll
            for (int nt = 0; nt < 3; nt++) {
                acc_o[mt][nt][0] *= alpha[mt][0];
                acc_o[mt][nt][1] *= alpha[mt][0];
                acc_o[mt][nt][2] *= alpha[mt][1];
                acc_o[mt][nt][3] *= alpha[mt][1];
            }
        }

#pragma unroll
        for (int mt = 0; mt < 4; mt++)
#pragma unroll
            for (int nt = 0; nt < 4; nt++) {
                int row = wr * 64 + mt * 16 + g;
                int col = wc * 32 + nt * 8 + 2 * tg;
                *(float2*)&Ks[row * FKP + col] = make_float2(sa[mt][nt][0], sa[mt][nt][1]);
                *(float2*)&Ks[(row + 8) * FKP + col] = make_float2(sa[mt][nt][2], sa[mt][nt][3]);
            }
        CP_WAIT(0);
        __syncthreads();

        const uint32_t* Pu = (const uint32_t*)Ks;
        const uint32_t* Vu = (const uint32_t*)Vs;
#pragma unroll
        for (int kk = 0; kk < 128; kk += 8) {
            uint32_t af[4][4], bf[3][2];
#pragma unroll
            for (int mt = 0; mt < 4; mt++) {
                int mb = wr * 64 + mt * 16 + g;
                af[mt][0] = Pu[mb * FKP + kk + tg];
                af[mt][1] = Pu[(mb + 8) * FKP + kk + tg];
                af[mt][2] = Pu[mb * FKP + kk + tg + 4];
                af[mt][3] = Pu[(mb + 8) * FKP + kk + tg + 4];
            }
#pragma unroll
            for (int nt = 0; nt < 3; nt++) {
                int nb = wc * 24 + nt * 8 + g;
                bf[nt][0] = Vu[(kk + tg) * FVP + nb];
                bf[nt][1] = Vu[(kk + tg + 4) * FVP + nb];
            }
#pragma unroll
            for (int mt = 0; mt < 4; mt++)
#pragma unroll
                for (int nt = 0; nt < 3; nt++)
                    mma_tf32(acc_o[mt][nt], af[mt], bf[nt]);
        }
        __syncthreads();
    }

#pragma unroll
    for (int mt = 0; mt < 4; mt++) {
        float inv0 = 1.f / l_i[mt][0];
        float inv1 = 1.f / l_i[mt][1];
#pragma unroll
        for (int nt = 0; nt < 3; nt++) {
            int row = m0 + wr * 64 + mt * 16 + g;
            int col = h * HD + wc * 24 + nt * 8 + 2 * tg;
            float* p0 = C + ((size_t)b * SS + row) * HH + col;
            float* p1 = C + ((size_t)b * SS + row + 8) * HH + col;
            *(float2*)p0 = make_float2(acc_o[mt][nt][0] * inv0, acc_o[mt][nt][1] * inv0);
            *(float2*)p1 = make_float2(acc_o[mt][nt][2] * inv1, acc_o[mt][nt][3] * inv1);
        }
    }
}

// ============================================================================
// ck GEMM + fused softmax.  BM=32, 512 threads (16 warps -> occ 43%).
// ============================================================================
__global__ void __launch_bounds__(512) ck_gemm_sm(
    const float* __restrict__ A, const float* __restrict__ W,
    const float* __restrict__ bias, float* __restrict__ C)
{
    __shared__ float As[32 * 68];
    __shared__ float Ws[64 * 60];
    __shared__ float S[32 * 57];
    const int tid = threadIdx.x;
    const int m0 = blockIdx.x * 32;
    const int rg = tid / 56, c = tid % 56;   // rg<8 active compute (448 threads)
    float acc[4];
#pragma unroll
    for (int r = 0; r < 4; r++) acc[r] = 0.f;

    for (int k0 = 0; k0 < AHd; k0 += 64) {
        {
            int f = tid;                          // 512 float4 = 2048 floats exactly
            int r = f >> 4, cc = (f & 15) << 2;
            *(float4*)&As[r * 68 + cc] = *(const float4*)(A + (size_t)(m0 + r) * AHd + k0 + cc);
        }
#pragma unroll
        for (int t = 0; t < 2; t++) {
            int f = tid + t * 512;
            if (f < 896) {
                int r = f / 14, cc = (f % 14) << 2;
                *(float4*)&Ws[r * 60 + cc] = *(const float4*)(W + (size_t)(k0 + r) * 56 + cc);
            }
        }
        __syncthreads();
        if (rg < 8) {
#pragma unroll
            for (int kk = 0; kk < 64; kk += 4) {
                float w0 = Ws[kk * 60 + c], w1 = Ws[(kk + 1) * 60 + c];
                float w2 = Ws[(kk + 2) * 60 + c], w3 = Ws[(kk + 3) * 60 + c];
#pragma unroll
                for (int r = 0; r < 4; r++) {
                    float4 a4 = *(const float4*)&As[(rg * 4 + r) * 68 + kk];
                    acc[r] += a4.x * w0 + a4.y * w1 + a4.z * w2 + a4.w * w3;
                }
            }
        }
        __syncthreads();
    }
    if (rg < 8) {
        float bb = bias[c];
#pragma unroll
        for (int r = 0; r < 4; r++)
            S[(rg * 4 + r) * 57 + c] = acc[r] + bb;
    }
    __syncthreads();
    if (tid < 256) {
        int row = tid >> 3, h = tid & 7;
        float* p = &S[row * 57 + h * 7];
        float m = p[0];
#pragma unroll
        for (int k = 1; k < 7; k++) m = fmaxf(m, p[k]);
        float e[7], s = 0.f;
#pragma unroll
        for (int k = 0; k < 7; k++) { e[k] = __expf(p[k] - m); s += e[k]; }
        float inv = 1.f / s;
        float* cp = C + (size_t)(m0 + row) * 56 + h * 7;
#pragma unroll
        for (int k = 0; k < 7; k++) cp[k] = e[k] * inv;
    }
}

// ---------------- depthwise conv: 8 outputs per thread ----------------
__global__ void depthwise_conv8(const float* __restrict__ X, const float* __restrict__ dw,
                                float* __restrict__ Y) {
    int idx = blockIdx.x * blockDim.x + threadIdx.x;
    if (idx >= (MROWS / 8) * HH) return;
    int c = idx % HH;
    int t = idx / HH;
    int sblk = t % (SS / 8);
    int b = t / (SS / 8);
    int s0 = sblk * 8;
    const float* xb = X + ((size_t)b * SS) * HH + c;
    float xv[14];
#pragma unroll
    for (int i = 0; i < 14; i++) {
        int ss = s0 - 3 + i;
        xv[i] = (ss >= 0 && ss < SS) ? xb[(size_t)ss * HH] : 0.f;
    }
    float w[7];
#pragma unroll
    for (int k = 0; k < 7; k++) w[k] = dw[c * 7 + k];
    float* yb = Y + ((size_t)b * SS + s0) * HH + c;
#pragma unroll
    for (int r = 0; r < 8; r++) {
        float acc = 0.f;
#pragma unroll
        for (int k = 0; k < 7; k++) acc += xv[r + k] * w[k];
        yb[(size_t)r * HH] = acc;
    }
}

// ---------------- span conv: 4 outputs per thread ----------------
__global__ void span_conv4(const float* __restrict__ co, const float* __restrict__ ck,
                           float* __restrict__ ctx) {
    int idx = blockIdx.x * blockDim.x + threadIdx.x;
    if (idx >= (MROWS / 4) * AHd) return;
    int col = idx % AHd;
    int t = idx / AHd;
    int sblk = t % (SS / 4);
    int b = t / (SS / 4);
    int h = col / HD;
    int s0 = sblk * 4;
    const float* cb = co + ((size_t)b * SS) * AHd + col;
    float cv[10];
#pragma unroll
    for (int i = 0; i < 10; i++) {
        int ss = s0 - 3 + i;
        cv[i] = (ss >= 0 && ss < SS) ? cb[(size_t)ss * AHd] : 0.f;
    }
    size_t row0 = (size_t)b * SS + s0;
#pragma unroll
    for (int r = 0; r < 4; r++) {
        const float* w = ck + (row0 + r) * 56 + h * 7;
        float acc = 0.f;
#pragma unroll
        for (int k = 0; k < 7; k++) acc += cv[r + k] * w[k];
        ctx[(row0 + r) * HH + AHd + col] = acc;
    }
}

// ---------------- fused residual + LayerNorm ----------------
__global__ void ln_residual(const float* __restrict__ X, const float* __restrict__ R,
                            const float* __restrict__ gam, const float* __restrict__ bet,
                            float* __restrict__ O) {
    size_t row = blockIdx.x;
    int tid = threadIdx.x;
    const float* x = X + row * HH;
    const float* r = R + row * HH;
    __shared__ float red[256];
    float vals[6];
    float s = 0.f;
#pragma unroll
    for (int t = 0; t < 6; t++) {
        int c = tid + t * 256;
        vals[t] = x[c] + r[c];
        s += vals[t];
    }
    red[tid] = s;
    __syncthreads();
    for (int o = 128; o > 0; o >>= 1) {
        if (tid < o) red[tid] += red[tid + o];
        __syncthreads();
    }
    float mean = red[0] * (1.f / HH);
    __syncthreads();
    float s2 = 0.f;
#pragma unroll
    for (int t = 0; t < 6; t++) {
        float d = vals[t] - mean;
        s2 += d * d;
    }
    red[tid] = s2;
    __syncthreads();
    for (int o = 128; o > 0; o >>= 1) {
        if (tid < o) red[tid] += red[tid + o];
        __syncthreads();
    }
    float rstd = rsqrtf(red[0] * (1.f / HH) + 1e-12f);
#pragma unroll
    for (int t = 0; t < 6; t++) {
        int c = tid + t * 256;
        O[row * HH + c] = (vals[t] - mean) * rstd * gam[c] + bet[c];
    }
}

// ---------------- split max-pool + decoder ----------------
__global__ void maxpool_part(const float* __restrict__ L, float* __restrict__ pp) {
    int idx = blockIdx.x * blockDim.x + threadIdx.x;
    if (idx >= MB * 8 * HH) return;
    int c = idx % HH;
    int ch = (idx / HH) & 7;
    int b = idx / (HH * 8);
    const float* base = L + ((size_t)b * SS + ch * 128) * HH + c;
    float m = -3.4e38f;
    for (int s = 0; s < 128; s++) m = fmaxf(m, base[(size_t)s * HH]);
    pp[idx] = m;
}

__global__ void decode2(const float* __restrict__ pp, const float* __restrict__ wd,
                        const float* __restrict__ bd, float* __restrict__ out) {
    int b = blockIdx.x;
    int tid = threadIdx.x;
    __shared__ float red[256];
    float part = 0.f;
    for (int c = tid; c < HH; c += 256) {
        float m = pp[((size_t)b * 8) * HH + c];
#pragma unroll
        for (int ch = 1; ch < 8; ch++)
            m = fmaxf(m, pp[((size_t)b * 8 + ch) * HH + c]);
        part += m * wd[c];
    }
    red[tid] = part;
    __syncthreads();
    for (int o = 128; o > 0; o >>= 1) {
        if (tid < o) red[tid] += red[tid + o];
        __syncthreads();
    }
    if (tid == 0) out[b] = red[0] + bd[0];
}

// ============================================================================
// Host launcher — two-stream overlap via event fork/join
// ============================================================================
extern "C" void kernel_launch(void* const* d_in, const int* in_sizes, int n_in,
                              void* d_out, int out_size) {
    const float* embed = (const float*)d_in[0];
    const float* wq  = (const float*)d_in[1];  const float* bq  = (const float*)d_in[2];
    const float* wk  = (const float*)d_in[3];  const float* bk  = (const float*)d_in[4];
    const float* wv  = (const float*)d_in[5];  const float* bv  = (const float*)d_in[6];
    const float* dw  = (const float*)d_in[7];
    const float* pw  = (const float*)d_in[8];  const float* sep_b = (const float*)d_in[9];
    const float* wck = (const float*)d_in[10]; const float* bck = (const float*)d_in[11];
    const float* wco = (const float*)d_in[12]; const float* bco = (const float*)d_in[13];
    const float* wso = (const float*)d_in[14]; const float* bso = (const float*)d_in[15];
    const float* ln1_g = (const float*)d_in[16]; const float* ln1_b = (const float*)d_in[17];
    const float* wi  = (const float*)d_in[18]; const float* bi  = (const float*)d_in[19];
    const float* wo  = (const float*)d_in[20]; const float* bo  = (const float*)d_in[21];
    const float* ln2_g = (const float*)d_in[22]; const float* ln2_b = (const float*)d_in[23];
    const float* wd  = (const float*)d_in[24]; const float* bd  = (const float*)d_in[25];
    float* out = (float*)d_out;

    cudaFuncSetAttribute(mma_gemm, cudaFuncAttributeMaxDynamicSharedMemorySize, GEMM_SMEM);
    cudaFuncSetAttribute(mma_gemm_multi, cudaFuncAttributeMaxDynamicSharedMemorySize, GEMM_SMEM);
    cudaFuncSetAttribute(flash_attn, cudaFuncAttributeMaxDynamicSharedMemorySize, FL_SMEM);

    float *q, *k, *v, *co, *dconv, *sep, *ck, *ctx, *tmp, *inter, *attn, *layer, *poolp;
    cudaGetSymbolAddress((void**)&q, g_q);
    cudaGetSymbolAddress((void**)&k, g_k);
    cudaGetSymbolAddress((void**)&v, g_v);
    cudaGetSymbolAddress((void**)&co, g_co);
    cudaGetSymbolAddress((void**)&dconv, g_dconv);
    cudaGetSymbolAddress((void**)&sep, g_sep);
    cudaGetSymbolAddress((void**)&ck, g_ck);
    cudaGetSymbolAddress((void**)&ctx, g_ctx);
    cudaGetSymbolAddress((void**)&tmp, g_tmp);
    cudaGetSymbolAddress((void**)&inter, g_inter);
    cudaGetSymbolAddress((void**)&attn, g_attn);
    cudaGetSymbolAddress((void**)&layer, g_layer);
    cudaGetSymbolAddress((void**)&poolp, g_poolp);

    dim3 blk(256);
    cudaStream_t s0 = 0;
    cudaStream_t s2 = g_si.s2;

    // ---- fork ----
    cudaEventRecord(g_si.evF, s0);
    cudaStreamWaitEvent(s2, g_si.evF, 0);

    // s2: depthwise conv — overlaps projections
    depthwise_conv8<<<((MROWS / 8) * HH + 255) / 256, blk, 0, s2>>>(embed, dw, dconv);

    // s0: fused q/k/v/co projections
    GemmSet sq = {wq, bq, q}, sk = {wk, bk, k}, sv = {wv, bv, v}, sc = {wco, bco, co};
    dim3 gm(AHd / 128, MROWS / 128, 4);
    mma_gemm_multi<<<gm, blk, GEMM_SMEM, s0>>>(embed, sq, sk, sv, sc, AHd, HH);
    cudaEventRecord(g_si.evA, s0);

    // s2: pw gemm -> ck (+softmax) -> span
    cudaStreamWaitEvent(s2, g_si.evA, 0);
    dim3 gproj(AHd / 128, MROWS / 128);
    mma_gemm<<<gproj, blk, GEMM_SMEM, s2>>>(dconv, pw, sep_b, sep, q, AHd, HH, 2);
    ck_gemm_sm<<<MROWS / 32, dim3(512), 0, s2>>>(sep, wck, bck, ck);
    span_conv4<<<((MROWS / 4) * AHd + 255) / 256, blk, 0, s2>>>(co, ck, ctx);
    cudaEventRecord(g_si.evB, s2);

    // s0: flash attention
    dim3 gfl(SS / 128, MB * NHh);
    flash_attn<<<gfl, blk, FL_SMEM, s0>>>(q, k, v, ctx);

    // join
    cudaStreamWaitEvent(s0, g_si.evB, 0);

    // ---- self output + LN1 ----
    dim3 gso(HH / 128, MROWS / 128);
    mma_gemm<<<gso, blk, GEMM_SMEM, s0>>>(ctx, wso, bso, tmp, nullptr, HH, HH, 0);
    ln_residual<<<MROWS, blk, 0, s0>>>(tmp, embed, ln1_g, ln1_b, attn);

    // ---- FFN ----
    dim3 gin(IM / 128, MROWS / 128);
    mma_gemm<<<gin, blk, GEMM_SMEM, s0>>>(attn, wi, bi, inter, nullptr, IM, HH, 1);
    mma_gemm<<<gso, blk, GEMM_SMEM, s0>>>(inter, wo, bo, tmp, nullptr, HH, IM, 0);
    ln_residual<<<MROWS, blk, 0, s0>>>(tmp, attn, ln2_g, ln2_b, layer);

    // ---- pool + decode ----
    maxpool_part<<<(MB * 8 * HH + 255) / 256, blk, 0, s0>>>(layer, poolp);
    decode2<<<MB, blk, 0, s0>>>(poolp, wd, bd, out);
}

// round 10
// speedup vs baseline: 1.0466x; 1.0466x over previous
#include <cuda_runtime.h>
#include <math.h>
#include <stdint.h>

// ---------------- problem dims ----------------
#define MB   8
#define SS   1024
#define HH   1536
#define NHh  8
#define HD   96
#define AHd  768
#define KK   7
#define IM   3072
#define MROWS (MB*SS)          // 8192

// ---------------- scratch ----------------
__device__ float g_q   [MROWS*AHd];
__device__ float g_k   [MROWS*AHd];
__device__ float g_v   [MROWS*AHd];
__device__ float g_co  [MROWS*AHd];
__device__ float g_dconv[MROWS*HH];
__device__ float g_sep [MROWS*AHd];
__device__ float g_ck  [MROWS*56];
__device__ float g_ctx [MROWS*HH];
__device__ float g_tmp [MROWS*HH];
__device__ float g_inter[MROWS*IM];
__device__ float g_attn[MROWS*HH];
__device__ float g_layer[MROWS*HH];
__device__ float g_poolp[MB*8*HH];

// ---------------- streams/events (created at load time) ----------------
struct StreamInit {
    cudaStream_t s2;
    cudaEvent_t evF, evA, evB;
    StreamInit() {
        cudaStreamCreateWithFlags(&s2, cudaStreamNonBlocking);
        cudaEventCreateWithFlags(&evF, cudaEventDisableTiming);
        cudaEventCreateWithFlags(&evA, cudaEventDisableTiming);
        cudaEventCreateWithFlags(&evB, cudaEventDisableTiming);
    }
};
static StreamInit g_si;

// ---------------- PTX helpers ----------------
__device__ __forceinline__ uint32_t sptr(const void* p) {
    return (uint32_t)__cvta_generic_to_shared(p);
}
#define CP16(dst, src) \
    asm volatile("cp.async.cg.shared.global [%0], [%1], 16;" :: "r"(dst), "l"(src))
#define CP_COMMIT() asm volatile("cp.async.commit_group;" ::: "memory")
#define CP_WAIT(n)  asm volatile("cp.async.wait_group %0;" :: "n"(n) : "memory")

__device__ __forceinline__ void mma_tf32(float* d, const uint32_t* a, const uint32_t* b) {
    asm volatile(
        "mma.sync.aligned.m16n8k8.row.col.f32.tf32.tf32.f32 "
        "{%0,%1,%2,%3}, {%4,%5,%6,%7}, {%8,%9}, {%0,%1,%2,%3};"
        : "+f"(d[0]), "+f"(d[1]), "+f"(d[2]), "+f"(d[3])
        : "r"(a[0]), "r"(a[1]), "r"(a[2]), "r"(a[3]), "r"(b[0]), "r"(b[1]));
}

// ============================================================================
// tf32 mma GEMM — R8-proven loop: 3-stage, wait(2), two syncs, issue after.
// op: 0 = bias, 1 = bias+gelu, 2 = (x+bias)*aux
// ============================================================================
#define PA   36
#define PB   136
#define ASZ  (128*PA)
#define BSZ  (32*PB)
#define NSTG 3
#define GEMM_SMEM (NSTG*(ASZ+BSZ)*4)

struct GemmSet { const float* W; const float* bias; float* C; };

__device__ __forceinline__ void gemm_body(
    const float* __restrict__ A, const float* __restrict__ W,
    const float* __restrict__ bias, float* __restrict__ C,
    const float* __restrict__ aux,
    int N, int Kd, int op, int m0, int n0, float* sm)
{
    float* Abase = sm;
    float* Bbase = sm + NSTG * ASZ;

    const int tid = threadIdx.x;
    const int wid = tid >> 5, lane = tid & 31;
    const int wr = wid >> 2, wc = wid & 3;
    const int g = lane >> 2, tg = lane & 3;
    const int nkb = Kd >> 5;

    float acc[4][4][4];
#pragma unroll
    for (int i = 0; i < 4; i++)
#pragma unroll
        for (int j = 0; j < 4; j++)
#pragma unroll
            for (int c = 0; c < 4; c++) acc[i][j][c] = 0.f;

    auto issue = [&](int kb) {
        int s = kb % NSTG;
        float* As = Abase + s * ASZ;
        float* Bs = Bbase + s * BSZ;
        const float* ag = A + (size_t)m0 * Kd + kb * 32;
        const float* bg = W + (size_t)(kb * 32) * N + n0;
#pragma unroll
        for (int t = 0; t < 4; t++) {
            int sA = tid + t * 256;
            int r  = sA >> 3,  c  = (sA & 7) << 2;
            CP16(sptr(As + r * PA + c), ag + (size_t)r * Kd + c);
            int rb = sA >> 5,  cb = (sA & 31) << 2;
            CP16(sptr(Bs + rb * PB + cb), bg + (size_t)rb * N + cb);
        }
    };

    issue(0); CP_COMMIT();
    issue(1); CP_COMMIT();
    issue(2); CP_COMMIT();

    for (int kb = 0; kb < nkb; kb++) {
        CP_WAIT(2);
        __syncthreads();
        int s = kb % NSTG;
        const uint32_t* As = (const uint32_t*)(Abase + s * ASZ);
        const uint32_t* Bs = (const uint32_t*)(Bbase + s * BSZ);
#pragma unroll
        for (int kk = 0; kk < 32; kk += 8) {
            uint32_t af[4][4], bf[4][2];
#pragma unroll
            for (int mt = 0; mt < 4; mt++) {
                int mb = wr * 64 + mt * 16 + g;
                af[mt][0] = As[mb * PA + kk + tg];
                af[mt][1] = As[(mb + 8) * PA + kk + tg];
                af[mt][2] = As[mb * PA + kk + tg + 4];
                af[mt][3] = As[(mb + 8) * PA + kk + tg + 4];
            }
#pragma unroll
            for (int nt = 0; nt < 4; nt++) {
                int nb = wc * 32 + nt * 8 + g;
                bf[nt][0] = Bs[(kk + tg) * PB + nb];
                bf[nt][1] = Bs[(kk + tg + 4) * PB + nb];
            }
#pragma unroll
            for (int mt = 0; mt < 4; mt++)
#pragma unroll
                for (int nt = 0; nt < 4; nt++)
                    mma_tf32(acc[mt][nt], af[mt], bf[nt]);
        }
        __syncthreads();
        if (kb + 3 < nkb) issue(kb + 3);
        CP_COMMIT();
    }

    float bb[4][2];
#pragma unroll
    for (int nt = 0; nt < 4; nt++) {
        int col = n0 + wc * 32 + nt * 8 + 2 * tg;
        bb[nt][0] = bias[col];
        bb[nt][1] = bias[col + 1];
    }
#pragma unroll
    for (int mt = 0; mt < 4; mt++) {
#pragma unroll
        for (int nt = 0; nt < 4; nt++) {
            int row = m0 + wr * 64 + mt * 16 + g;
            int col = n0 + wc * 32 + nt * 8 + 2 * tg;
            float v0 = acc[mt][nt][0] + bb[nt][0];
            float v1 = acc[mt][nt][1] + bb[nt][1];
            float v2 = acc[mt][nt][2] + bb[nt][0];
            float v3 = acc[mt][nt][3] + bb[nt][1];
            if (op == 1) {
                v0 = 0.5f * v0 * (1.f + erff(v0 * 0.70710678118654752f));
                v1 = 0.5f * v1 * (1.f + erff(v1 * 0.70710678118654752f));
                v2 = 0.5f * v2 * (1.f + erff(v2 * 0.70710678118654752f));
                v3 = 0.5f * v3 * (1.f + erff(v3 * 0.70710678118654752f));
            } else if (op == 2) {
                const float* a0 = aux + (size_t)row * N + col;
                const float* a1 = aux + (size_t)(row + 8) * N + col;
                v0 *= a0[0]; v1 *= a0[1]; v2 *= a1[0]; v3 *= a1[1];
            }
            *(float2*)(C + (size_t)row * N + col)       = make_float2(v0, v1);
            *(float2*)(C + (size_t)(row + 8) * N + col) = make_float2(v2, v3);
        }
    }
}

__global__ void __launch_bounds__(256, 2) mma_gemm(
    const float* __restrict__ A, const float* __restrict__ W,
    const float* __restrict__ bias, float* __restrict__ C,
    const float* __restrict__ aux, int N, int Kd, int op)
{
    extern __shared__ float sm[];
    gemm_body(A, W, bias, C, aux, N, Kd, op, blockIdx.y * 128, blockIdx.x * 128, sm);
}

__global__ void __launch_bounds__(256, 2) mma_gemm_multi(
    const float* __restrict__ A, GemmSet s0, GemmSet s1, GemmSet s2, GemmSet s3,
    int N, int Kd)
{
    extern __shared__ float sm[];
    GemmSet s = (blockIdx.z == 0) ? s0 : (blockIdx.z == 1) ? s1 : (blockIdx.z == 2) ? s2 : s3;
    gemm_body(A, s.W, s.bias, s.C, nullptr, N, Kd, 0, blockIdx.y * 128, blockIdx.x * 128, sm);
}

// ============================================================================
// Fused flash attention (unchanged)
// ============================================================================
#define FQP 100
#define FKP 132
#define FVP 104
#define FL_SMEM ((128*FQP + 128*FKP + 128*FVP + 2*128*4)*4)

__global__ void __launch_bounds__(256) flash_attn(
    const float* __restrict__ Q, const float* __restrict__ K,
    const float* __restrict__ V, float* __restrict__ C)
{
    extern __shared__ float sm[];
    float* Qs   = sm;
    float* Ks   = Qs + 128 * FQP;
    float* Vs   = Ks + 128 * FKP;
    float* redm = Vs + 128 * FVP;
    float* reds = redm + 128 * 4;

    const int tid = threadIdx.x;
    const int wid = tid >> 5, lane = tid & 31;
    const int wr = wid >> 2, wc = wid & 3;
    const int g = lane >> 2, tg = lane & 3;
    const int bz = blockIdx.y, b = bz >> 3, h = bz & 7;
    const int m0 = blockIdx.x * 128;

    const float* qg = Q + (size_t)b * SS * AHd + h * HD;
    const float* kg = K + (size_t)b * SS * AHd + h * HD;
    const float* vg = V + (size_t)b * SS * AHd + h * HD;

#pragma unroll
    for (int t = 0; t < 12; t++) {
        int s = tid + t * 256;
        int r = s / 24, cc = (s % 24) * 4;
        CP16(sptr(Qs + r * FQP + cc), qg + (size_t)(m0 + r) * AHd + cc);
    }
    CP_COMMIT();

    float m_i[4][2], l_i[4][2];
    float acc_o[4][3][4];
#pragma unroll
    for (int i = 0; i < 4; i++) {
        m_i[i][0] = m_i[i][1] = -1e30f;
        l_i[i][0] = l_i[i][1] = 0.f;
#pragma unroll
        for (int j = 0; j < 3; j++)
#pragma unroll
            for (int c = 0; c < 4; c++) acc_o[i][j][c] = 0.f;
    }

    for (int kt = 0; kt < 8; kt++) {
#pragma unroll
        for (int t = 0; t < 12; t++) {
            int s = tid + t * 256;
            int r = s / 24, cc = (s % 24) * 4;
            CP16(sptr(Ks + r * FKP + cc), kg + (size_t)(kt * 128 + r) * AHd + cc);
        }
        CP_COMMIT();
#pragma unroll
        for (int t = 0; t < 12; t++) {
            int s = tid + t * 256;
            int r = s / 24, cc = (s % 24) * 4;
            CP16(sptr(Vs + r * FVP + cc), vg + (size_t)(kt * 128 + r) * AHd + cc);
        }
        CP_COMMIT();
        CP_WAIT(1);
        __syncthreads();

        float sa[4][4][4];
#pragma unroll
        for (int i = 0; i < 4; i++)
#pragma unroll
            for (int j = 0; j < 4; j++)
#pragma unroll
                for (int c = 0; c < 4; c++) sa[i][j][c] = 0.f;

        const uint32_t* Qu = (const uint32_t*)Qs;
        const uint32_t* Ku = (const uint32_t*)Ks;
#pragma unroll
        for (int kk = 0; kk < 96; kk += 8) {
            uint32_t af[4][4], bf[4][2];
#pragma unroll
            for (int mt = 0; mt < 4; mt++) {
                int mb = wr * 64 + mt * 16 + g;
                af[mt][0] = Qu[mb * FQP + kk + tg];
                af[mt][1] = Qu[(mb + 8) * FQP + kk + tg];
                af[mt][2] = Qu[mb * FQP + kk + tg + 4];
                af[mt][3] = Qu[(mb + 8) * FQP + kk + tg + 4];
            }
#pragma unroll
            for (int nt = 0; nt < 4; nt++) {
                int nb = wc * 32 + nt * 8 + g;
                bf[nt][0] = Ku[nb * FKP + kk + tg];
                bf[nt][1] = Ku[nb * FKP + kk + tg + 4];
            }
#pragma unroll
            for (int mt = 0; mt < 4; mt++)
#pragma unroll
                for (int nt = 0; nt < 4; nt++)
                    mma_tf32(sa[mt][nt], af[mt], bf[nt]);
        }
        const float scale = 0.10206207261596576f;
#pragma unroll
        for (int mt = 0; mt < 4; mt++)
#pragma unroll
            for (int nt = 0; nt < 4; nt++)
#pragma unroll
                for (int c = 0; c < 4; c++) sa[mt][nt][c] *= scale;

        float rmax[4][2];
#pragma unroll
        for (int mt = 0; mt < 4; mt++) {
            float m0v = fmaxf(sa[mt][0][0], sa[mt][0][1]);
            float m1v = fmaxf(sa[mt][0][2], sa[mt][0][3]);
#pragma unroll
            for (int nt = 1; nt < 4; nt++) {
                m0v = fmaxf(m0v, fmaxf(sa[mt][nt][0], sa[mt][nt][1]));
                m1v = fmaxf(m1v, fmaxf(sa[mt][nt][2], sa[mt][nt][3]));
            }
            m0v = fmaxf(m0v, __shfl_xor_sync(0xffffffffu, m0v, 1));
            m0v = fmaxf(m0v, __shfl_xor_sync(0xffffffffu, m0v, 2));
            m1v = fmaxf(m1v, __shfl_xor_sync(0xffffffffu, m1v, 1));
            m1v = fmaxf(m1v, __shfl_xor_sync(0xffffffffu, m1v, 2));
            rmax[mt][0] = m0v; rmax[mt][1] = m1v;
        }
        if (tg == 0) {
#pragma unroll
            for (int mt = 0; mt < 4; mt++) {
                int r0 = wr * 64 + mt * 16 + g;
                redm[r0 * 4 + wc] = rmax[mt][0];
                redm[(r0 + 8) * 4 + wc] = rmax[mt][1];
            }
        }
        __syncthreads();

        float alpha[4][2], mnew[4][2];
#pragma unroll
        for (int mt = 0; mt < 4; mt++) {
#pragma unroll
            for (int hf = 0; hf < 2; hf++) {
                int row = wr * 64 + mt * 16 + g + hf * 8;
                float4 r4 = *(float4*)&redm[row * 4];
                float gm = fmaxf(fmaxf(r4.x, r4.y), fmaxf(r4.z, r4.w));
                float mn = fmaxf(m_i[mt][hf], gm);
                alpha[mt][hf] = __expf(m_i[mt][hf] - mn);
                mnew[mt][hf] = mn;
                m_i[mt][hf] = mn;
            }
        }

        float rsum[4][2];
#pragma unroll
        for (int mt = 0; mt < 4; mt++) { rsum[mt][0] = 0.f; rsum[mt][1] = 0.f; }
#pragma unroll
        for (int mt = 0; mt < 4; mt++)
#pragma unroll
            for (int nt = 0; nt < 4; nt++) {
                sa[mt][nt][0] = __expf(sa[mt][nt][0] - mnew[mt][0]);
                sa[mt][nt][1] = __expf(sa[mt][nt][1] - mnew[mt][0]);
                sa[mt][nt][2] = __expf(sa[mt][nt][2] - mnew[mt][1]);
                sa[mt][nt][3] = __expf(sa[mt][nt][3] - mnew[mt][1]);
                rsum[mt][0] += sa[mt][nt][0] + sa[mt][nt][1];
                rsum[mt][1] += sa[mt][nt][2] + sa[mt][nt][3];
            }
#pragma unroll
        for (int mt = 0; mt < 4; mt++) {
            rsum[mt][0] += __shfl_xor_sync(0xffffffffu, rsum[mt][0], 1);
            rsum[mt][0] += __shfl_xor_sync(0xffffffffu, rsum[mt][0], 2);
            rsum[mt][1] += __shfl_xor_sync(0xffffffffu, rsum[mt][1], 1);
            rsum[mt][1] += __shfl_xor_sync(0xffffffffu, rsum[mt][1], 2);
        }
        if (tg == 0) {
#pragma unroll
            for (int mt = 0; mt < 4; mt++) {
                int r0 = wr * 64 + mt * 16 + g;
                reds[r0 * 4 + wc] = rsum[mt][0];
                reds[(r0 + 8) * 4 + wc] = rsum[mt][1];
            }
        }
        __syncthreads();
#pragma unroll
        for (int mt = 0; mt < 4; mt++) {
#pragma unroll
            for (int hf = 0; hf < 2; hf++) {
                int row = wr * 64 + mt * 16 + g + hf * 8;
                float4 r4 = *(float4*)&reds[row * 4];
                float rs = r4.x + r4.y + r4.z + r4.w;
                l_i[mt][hf] = l_i[mt][hf] * alpha[mt][hf] + rs;
            }
#pragma unroll
            for (int nt = 0; nt < 3; nt++) {
                acc_o[mt][nt][0] *= alpha[mt][0];
                acc_o[mt][nt][1] *= alpha[mt][0];
                acc_o[mt][nt][2] *= alpha[mt][1];
                acc_o[mt][nt][3] *= alpha[mt][1];
            }
        }

#pragma unroll
        for (int mt = 0; mt < 4; mt++)
#pragma unroll
            for (int nt = 0; nt < 4; nt++) {
                int row = wr * 64 + mt * 16 + g;
                int col = wc * 32 + nt * 8 + 2 * tg;
                *(float2*)&Ks[row * FKP + col] = make_float2(sa[mt][nt][0], sa[mt][nt][1]);
                *(float2*)&Ks[(row + 8) * FKP + col] = make_float2(sa[mt][nt][2], sa[mt][nt][3]);
            }
        CP_WAIT(0);
        __syncthreads();

        const uint32_t* Pu = (const uint32_t*)Ks;
        const uint32_t* Vu = (const uint32_t*)Vs;
#pragma unroll
        for (int kk = 0; kk < 128; kk += 8) {
            uint32_t af[4][4], bf[3][2];
#pragma unroll
            for (int mt = 0; mt < 4; mt++) {
                int mb = wr * 64 + mt * 16 + g;
                af[mt][0] = Pu[mb * FKP + kk + tg];
                af[mt][1] = Pu[(mb + 8) * FKP + kk + tg];
                af[mt][2] = Pu[mb * FKP + kk + tg + 4];
                af[mt][3] = Pu[(mb + 8) * FKP + kk + tg + 4];
            }
#pragma unroll
            for (int nt = 0; nt < 3; nt++) {
                int nb = wc * 24 + nt * 8 + g;
                bf[nt][0] = Vu[(kk + tg) * FVP + nb];
                bf[nt][1] = Vu[(kk + tg + 4) * FVP + nb];
            }
#pragma unroll
            for (int mt = 0; mt < 4; mt++)
#pragma unroll
                for (int nt = 0; nt < 3; nt++)
                    mma_tf32(acc_o[mt][nt], af[mt], bf[nt]);
        }
        __syncthreads();
    }

#pragma unroll
    for (int mt = 0; mt < 4; mt++) {
        float inv0 = 1.f / l_i[mt][0];
        float inv1 = 1.f / l_i[mt][1];
#pragma unroll
        for (int nt = 0; nt < 3; nt++) {
            int row = m0 + wr * 64 + mt * 16 + g;
            int col = h * HD + wc * 24 + nt * 8 + 2 * tg;
            float* p0 = C + ((size_t)b * SS + row) * HH + col;
            float* p1 = C + ((size_t)b * SS + row + 8) * HH + col;
            *(float2*)p0 = make_float2(acc_o[mt][nt][0] * inv0, acc_o[mt][nt][1] * inv0);
            *(float2*)p1 = make_float2(acc_o[mt][nt][2] * inv1, acc_o[mt][nt][3] * inv1);
        }
    }
}

// ============================================================================
// ck GEMM + fused softmax.  BM=32, 256 threads, cp.async double-buffered.
// ============================================================================
#define CKA (32*68)
#define CKW (64*60)
#define CK_SMEM ((2*CKA + 2*CKW + 32*57)*4)

__global__ void __launch_bounds__(256) ck_gemm_sm(
    const float* __restrict__ A, const float* __restrict__ W,
    const float* __restrict__ bias, float* __restrict__ C)
{
    extern __shared__ float cksm[];
    float* As = cksm;                 // [2][32*68]
    float* Ws = cksm + 2 * CKA;       // [2][64*60]
    float* S  = cksm + 2 * CKA + 2 * CKW;  // [32*57]

    const int tid = threadIdx.x;
    const int m0 = blockIdx.x * 32;
    const int rg = tid / 56, c = tid % 56;
    float acc[8];
#pragma unroll
    for (int r = 0; r < 8; r++) acc[r] = 0.f;

    auto issue = [&](int t) {
        int buf = t & 1;
        int k0 = t * 64;
        float* Ab = As + buf * CKA;
        float* Wb = Ws + buf * CKW;
#pragma unroll
        for (int u = 0; u < 2; u++) {
            int f = tid + u * 256;
            int r = f >> 4, cc = (f & 15) << 2;
            CP16(sptr(Ab + r * 68 + cc), A + (size_t)(m0 + r) * AHd + k0 + cc);
        }
#pragma unroll
        for (int u = 0; u < 4; u++) {
            int f = tid + u * 256;
            if (f < 896) {
                int r = f / 14, cc = (f % 14) << 2;
                CP16(sptr(Wb + r * 60 + cc), W + (size_t)(k0 + r) * 56 + cc);
            }
        }
    };

    issue(0); CP_COMMIT();
    for (int t = 0; t < 12; t++) {
        if (t + 1 < 12) { issue(t + 1); CP_COMMIT(); }
        if (t + 1 < 12) { CP_WAIT(1); } else { CP_WAIT(0); }
        __syncthreads();
        int buf = t & 1;
        const float* Ab = As + buf * CKA;
        const float* Wb = Ws + buf * CKW;
        if (rg < 4) {
#pragma unroll
            for (int kk = 0; kk < 64; kk += 4) {
                float w0 = Wb[kk * 60 + c], w1 = Wb[(kk + 1) * 60 + c];
                float w2 = Wb[(kk + 2) * 60 + c], w3 = Wb[(kk + 3) * 60 + c];
#pragma unroll
                for (int r = 0; r < 8; r++) {
                    float4 a4 = *(const float4*)&Ab[(rg * 8 + r) * 68 + kk];
                    acc[r] += a4.x * w0 + a4.y * w1 + a4.z * w2 + a4.w * w3;
                }
            }
        }
        __syncthreads();
    }
    if (rg < 4) {
        float bb = bias[c];
#pragma unroll
        for (int r = 0; r < 8; r++)
            S[(rg * 8 + r) * 57 + c] = acc[r] + bb;
    }
    __syncthreads();
    {
        int row = tid >> 3, h = tid & 7;
        float* p = &S[row * 57 + h * 7];
        float m = p[0];
#pragma unroll
        for (int k = 1; k < 7; k++) m = fmaxf(m, p[k]);
        float e[7], s = 0.f;
#pragma unroll
        for (int k = 0; k < 7; k++) { e[k] = __expf(p[k] - m); s += e[k]; }
        float inv = 1.f / s;
        float* cp = C + (size_t)(m0 + row) * 56 + h * 7;
#pragma unroll
        for (int k = 0; k < 7; k++) cp[k] = e[k] * inv;
    }
}

// ---------------- depthwise conv: 8 outputs per thread ----------------
__global__ void depthwise_conv8(const float* __restrict__ X, const float* __restrict__ dw,
                                float* __restrict__ Y) {
    int idx = blockIdx.x * blockDim.x + threadIdx.x;
    if (idx >= (MROWS / 8) * HH) return;
    int c = idx % HH;
    int t = idx / HH;
    int sblk = t % (SS / 8);
    int b = t / (SS / 8);
    int s0 = sblk * 8;
    const float* xb = X + ((size_t)b * SS) * HH + c;
    float xv[14];
#pragma unroll
    for (int i = 0; i < 14; i++) {
        int ss = s0 - 3 + i;
        xv[i] = (ss >= 0 && ss < SS) ? xb[(size_t)ss * HH] : 0.f;
    }
    float w[7];
#pragma unroll
    for (int k = 0; k < 7; k++) w[k] = dw[c * 7 + k];
    float* yb = Y + ((size_t)b * SS + s0) * HH + c;
#pragma unroll
    for (int r = 0; r < 8; r++) {
        float acc = 0.f;
#pragma unroll
        for (int k = 0; k < 7; k++) acc += xv[r + k] * w[k];
        yb[(size_t)r * HH] = acc;
    }
}

// ---------------- span conv: 4 outputs per thread ----------------
__global__ void span_conv4(const float* __restrict__ co, const float* __restrict__ ck,
                           float* __restrict__ ctx) {
    int idx = blockIdx.x * blockDim.x + threadIdx.x;
    if (idx >= (MROWS / 4) * AHd) return;
    int col = idx % AHd;
    int t = idx / AHd;
    int sblk = t % (SS / 4);
    int b = t / (SS / 4);
    int h = col / HD;
    int s0 = sblk * 4;
    const float* cb = co + ((size_t)b * SS) * AHd + col;
    float cv[10];
#pragma unroll
    for (int i = 0; i < 10; i++) {
        int ss = s0 - 3 + i;
        cv[i] = (ss >= 0 && ss < SS) ? cb[(size_t)ss * AHd] : 0.f;
    }
    size_t row0 = (size_t)b * SS + s0;
#pragma unroll
    for (int r = 0; r < 4; r++) {
        const float* w = ck + (row0 + r) * 56 + h * 7;
        float acc = 0.f;
#pragma unroll
        for (int k = 0; k < 7; k++) acc += cv[r + k] * w[k];
        ctx[(row0 + r) * HH + AHd + col] = acc;
    }
}

// ---------------- fused residual + LayerNorm (shuffle reductions) ----------------
__global__ void ln_residual(const float* __restrict__ X, const float* __restrict__ R,
                            const float* __restrict__ gam, const float* __restrict__ bet,
                            float* __restrict__ O) {
    size_t row = blockIdx.x;
    int tid = threadIdx.x;
    int lane = tid & 31, wid = tid >> 5;
    const float* x = X + row * HH;
    const float* r = R + row * HH;
    __shared__ float w1[8], w2[8];
    float vals[6];
    float s = 0.f;
#pragma unroll
    for (int t = 0; t < 6; t++) {
        int c = tid + t * 256;
        vals[t] = x[c] + r[c];
        s += vals[t];
    }
#pragma unroll
    for (int o = 16; o > 0; o >>= 1) s += __shfl_xor_sync(0xffffffffu, s, o);
    if (lane == 0) w1[wid] = s;
    __syncthreads();
    float tot = 0.f;
#pragma unroll
    for (int i = 0; i < 8; i++) tot += w1[i];
    float mean = tot * (1.f / HH);

    float s2 = 0.f;
#pragma unroll
    for (int t = 0; t < 6; t++) {
        float d = vals[t] - mean;
        s2 += d * d;
    }
#pragma unroll
    for (int o = 16; o > 0; o >>= 1) s2 += __shfl_xor_sync(0xffffffffu, s2, o);
    if (lane == 0) w2[wid] = s2;
    __syncthreads();
    float tot2 = 0.f;
#pragma unroll
    for (int i = 0; i < 8; i++) tot2 += w2[i];
    float rstd = rsqrtf(tot2 * (1.f / HH) + 1e-12f);
#pragma unroll
    for (int t = 0; t < 6; t++) {
        int c = tid + t * 256;
        O[row * HH + c] = (vals[t] - mean) * rstd * gam[c] + bet[c];
    }
}

// ---------------- split max-pool + decoder ----------------
__global__ void maxpool_part(const float* __restrict__ L, float* __restrict__ pp) {
    int idx = blockIdx.x * blockDim.x + threadIdx.x;
    if (idx >= MB * 8 * HH) return;
    int c = idx % HH;
    int ch = (idx / HH) & 7;
    int b = idx / (HH * 8);
    const float* base = L + ((size_t)b * SS + ch * 128) * HH + c;
    float m = -3.4e38f;
    for (int s = 0; s < 128; s++) m = fmaxf(m, base[(size_t)s * HH]);
    pp[idx] = m;
}

__global__ void decode2(const float* __restrict__ pp, const float* __restrict__ wd,
                        const float* __restrict__ bd, float* __restrict__ out) {
    int b = blockIdx.x;
    int tid = threadIdx.x;
    __shared__ float red[256];
    float part = 0.f;
    for (int c = tid; c < HH; c += 256) {
        float m = pp[((size_t)b * 8) * HH + c];
#pragma unroll
        for (int ch = 1; ch < 8; ch++)
            m = fmaxf(m, pp[((size_t)b * 8 + ch) * HH + c]);
        part += m * wd[c];
    }
    red[tid] = part;
    __syncthreads();
    for (int o = 128; o > 0; o >>= 1) {
        if (tid < o) red[tid] += red[tid + o];
        __syncthreads();
    }
    if (tid == 0) out[b] = red[0] + bd[0];
}

// ============================================================================
// Host launcher — two-stream overlap via event fork/join
// ============================================================================
extern "C" void kernel_launch(void* const* d_in, const int* in_sizes, int n_in,
                              void* d_out, int out_size) {
    const float* embed = (const float*)d_in[0];
    const float* wq  = (const float*)d_in[1];  const float* bq  = (const float*)d_in[2];
    const float* wk  = (const float*)d_in[3];  const float* bk  = (const float*)d_in[4];
    const float* wv  = (const float*)d_in[5];  const float* bv  = (const float*)d_in[6];
    const float* dw  = (const float*)d_in[7];
    const float* pw  = (const float*)d_in[8];  const float* sep_b = (const float*)d_in[9];
    const float* wck = (const float*)d_in[10]; const float* bck = (const float*)d_in[11];
    const float* wco = (const float*)d_in[12]; const float* bco = (const float*)d_in[13];
    const float* wso = (const float*)d_in[14]; const float* bso = (const float*)d_in[15];
    const float* ln1_g = (const float*)d_in[16]; const float* ln1_b = (const float*)d_in[17];
    const float* wi  = (const float*)d_in[18]; const float* bi  = (const float*)d_in[19];
    const float* wo  = (const float*)d_in[20]; const float* bo  = (const float*)d_in[21];
    const float* ln2_g = (const float*)d_in[22]; const float* ln2_b = (const float*)d_in[23];
    const float* wd  = (const float*)d_in[24]; const float* bd  = (const float*)d_in[25];
    float* out = (float*)d_out;

    cudaFuncSetAttribute(mma_gemm, cudaFuncAttributeMaxDynamicSharedMemorySize, GEMM_SMEM);
    cudaFuncSetAttribute(mma_gemm_multi, cudaFuncAttributeMaxDynamicSharedMemorySize, GEMM_SMEM);
    cudaFuncSetAttribute(flash_attn, cudaFuncAttributeMaxDynamicSharedMemorySize, FL_SMEM);
    cudaFuncSetAttribute(ck_gemm_sm, cudaFuncAttributeMaxDynamicSharedMemorySize, CK_SMEM);

    float *q, *k, *v, *co, *dconv, *sep, *ck, *ctx, *tmp, *inter, *attn, *layer, *poolp;
    cudaGetSymbolAddress((void**)&q, g_q);
    cudaGetSymbolAddress((void**)&k, g_k);
    cudaGetSymbolAddress((void**)&v, g_v);
    cudaGetSymbolAddress((void**)&co, g_co);
    cudaGetSymbolAddress((void**)&dconv, g_dconv);
    cudaGetSymbolAddress((void**)&sep, g_sep);
    cudaGetSymbolAddress((void**)&ck, g_ck);
    cudaGetSymbolAddress((void**)&ctx, g_ctx);
    cudaGetSymbolAddress((void**)&tmp, g_tmp);
    cudaGetSymbolAddress((void**)&inter, g_inter);
    cudaGetSymbolAddress((void**)&attn, g_attn);
    cudaGetSymbolAddress((void**)&layer, g_layer);
    cudaGetSymbolAddress((void**)&poolp, g_poolp);

    dim3 blk(256);
    cudaStream_t s0 = 0;
    cudaStream_t s2 = g_si.s2;

    // ---- fork ----
    cudaEventRecord(g_si.evF, s0);
    cudaStreamWaitEvent(s2, g_si.evF, 0);

    // s2: depthwise conv — overlaps projections
    depthwise_conv8<<<((MROWS / 8) * HH + 255) / 256, blk, 0, s2>>>(embed, dw, dconv);

    // s0: fused q/k/v/co projections
    GemmSet sq = {wq, bq, q}, sk = {wk, bk, k}, sv = {wv, bv, v}, sc = {wco, bco, co};
    dim3 gm(AHd / 128, MROWS / 128, 4);
    mma_gemm_multi<<<gm, blk, GEMM_SMEM, s0>>>(embed, sq, sk, sv, sc, AHd, HH);
    cudaEventRecord(g_si.evA, s0);

    // s2: pw gemm -> ck (+softmax) -> span
    cudaStreamWaitEvent(s2, g_si.evA, 0);
    dim3 gproj(AHd / 128, MROWS / 128);
    mma_gemm<<<gproj, blk, GEMM_SMEM, s2>>>(dconv, pw, sep_b, sep, q, AHd, HH, 2);
    ck_gemm_sm<<<MROWS / 32, blk, CK_SMEM, s2>>>(sep, wck, bck, ck);
    span_conv4<<<((MROWS / 4) * AHd + 255) / 256, blk, 0, s2>>>(co, ck, ctx);
    cudaEventRecord(g_si.evB, s2);

    // s0: flash attention
    dim3 gfl(SS / 128, MB * NHh);
    flash_attn<<<gfl, blk, FL_SMEM, s0>>>(q, k, v, ctx);

    // join
    cudaStreamWaitEvent(s0, g_si.evB, 0);

    // ---- self output + LN1 ----
    dim3 gso(HH / 128, MROWS / 128);
    mma_gemm<<<gso, blk, GEMM_SMEM, s0>>>(ctx, wso, bso, tmp, nullptr, HH, HH, 0);
    ln_residual<<<MROWS, blk, 0, s0>>>(tmp, embed, ln1_g, ln1_b, attn);

    // ---- FFN ----
    dim3 gin(IM / 128, MROWS / 128);
    mma_gemm<<<gin, blk, GEMM_SMEM, s0>>>(attn, wi, bi, inter, nullptr, IM, HH, 1);
    mma_gemm<<<gso, blk, GEMM_SMEM, s0>>>(inter, wo, bo, tmp, nullptr, HH, IM, 0);
    ln_residual<<<MROWS, blk, 0, s0>>>(tmp, attn, ln2_g, ln2_b, layer);

    // ---- pool + decode ----
    maxpool_part<<<(MB * 8 * HH + 255) / 256, blk, 0, s0>>>(layer, poolp);
    decode2<<<MB, blk, 0, s0>>>(poolp, wd, bd, out);
}